// round 5
// baseline (speedup 1.0000x reference)
#include <cuda_runtime.h>

#define BN    16384   // number of segments (power of two)
#define TPB   256     // threads per block
#define ITEMS 32      // strided elements per thread -> 1024 nodes per warp tile
#define U     8       // load-batching chunk

// Scratch (no cudaMalloc). Zero-initialized at module load; mlp_kernel
// re-zeroes after consuming so every launch/replay starts from zeros.
__device__ float4 g_sum[BN];
__device__ float  g_cnt[BN];

// Predicated flush: 5 guarded red.global.add, NO branch (ptxas won't emit
// 0-BSSY predicated atomics from C++ if{}; inline PTX forces it).
// No "memory" clobber on purpose: nothing in this kernel reads g_sum/g_cnt,
// and keeping the clobber out lets the compiler batch the x/batch loads
// across flush sites.
__device__ __forceinline__ void flush_if(int pred, int seg,
                                         const float4 a, float c) {
    float* s  = &g_sum[seg & (BN - 1)].x;
    float* cn = &g_cnt[seg & (BN - 1)];
    asm volatile(
        "{\n\t"
        ".reg .pred p;\n\t"
        "setp.ne.s32 p, %0, 0;\n\t"
        "@p red.global.add.f32 [%1],    %3;\n\t"
        "@p red.global.add.f32 [%1+4],  %4;\n\t"
        "@p red.global.add.f32 [%1+8],  %5;\n\t"
        "@p red.global.add.f32 [%1+12], %6;\n\t"
        "@p red.global.add.f32 [%2],    %7;\n\t"
        "}"
        :: "r"(pred), "l"(s), "l"(cn),
           "f"(a.x), "f"(a.y), "f"(a.z), "f"(a.w), "f"(c));
}

__global__ void __launch_bounds__(TPB) seg_reduce_kernel(
    const float4* __restrict__ x,
    const int*    __restrict__ batch,
    int n)
{
    const int lane = threadIdx.x & 31;
    const int warp = blockIdx.x * (TPB / 32) + (threadIdx.x >> 5);
    const int base = warp * (32 * ITEMS);
    if (base >= n) return;

    float4 acc = make_float4(0.f, 0.f, 0.f, 0.f);
    float  cnt = 0.f;

    if (base + 32 * ITEMS <= n) {
        // ---- fast path: fully branch-free body ----
        int cur = batch[base + lane];   // peek; re-hits in L1 for chunk 0
        #pragma unroll
        for (int c0 = 0; c0 < ITEMS; c0 += U) {
            int    bs[U];
            float4 vs[U];
            #pragma unroll
            for (int j = 0; j < U; ++j) {
                int idx = base + (c0 + j) * 32 + lane;
                bs[j] = batch[idx];
                vs[j] = x[idx];
            }
            #pragma unroll
            for (int j = 0; j < U; ++j) {
                int neq = bs[j] - cur;              // nonzero at a boundary
                flush_if(neq, cur, acc, cnt);       // predicated, no branch
                float m = (neq == 0) ? 1.f : 0.f;   // keep-mask
                acc.x = fmaf(m, acc.x, vs[j].x);
                acc.y = fmaf(m, acc.y, vs[j].y);
                acc.z = fmaf(m, acc.z, vs[j].z);
                acc.w = fmaf(m, acc.w, vs[j].w);
                cnt   = fmaf(m, cnt, 1.f);
                cur   = bs[j];
            }
        }
        flush_if(1, cur, acc, cnt);
    } else {
        // ---- tail path: per-element bounds checks (one warp only) ----
        int cur = -1;
        for (int it = 0; it < ITEMS; ++it) {
            int idx = base + it * 32 + lane;
            if (idx >= n) break;
            int    b = batch[idx];
            float4 v = x[idx];
            if (b == cur) {
                acc.x += v.x; acc.y += v.y; acc.z += v.z; acc.w += v.w;
                cnt   += 1.f;
            } else {
                if (cnt > 0.f) flush_if(1, cur, acc, cnt);
                cur = b;
                acc = v;
                cnt = 1.f;
            }
        }
        if (cnt > 0.f) flush_if(1, cur, acc, cnt);
    }
}

// Tiny MLP: h = concat(u, mean)[5]; leaky_relu(h@W1+b1, 0.1); @W2+b2 -> out[B,1]
// Also resets the scratch accumulators for the next graph replay.
__global__ void __launch_bounds__(TPB) mlp_kernel(
    const float* __restrict__ u,
    const float* __restrict__ W1,  // [5,5] row-major
    const float* __restrict__ b1,  // [5]
    const float* __restrict__ W2,  // [5,1]
    const float* __restrict__ b2,  // [1]
    float* __restrict__ out)
{
    int i = blockIdx.x * blockDim.x + threadIdx.x;
    if (i >= BN) return;

    float  c  = g_cnt[i];
    float4 sv = g_sum[i];
    float inv = (c > 0.f) ? (1.f / c) : 0.f;

    float h[5];
    h[0] = __ldg(&u[i]);
    h[1] = sv.x * inv; h[2] = sv.y * inv;
    h[3] = sv.z * inv; h[4] = sv.w * inv;

    float o = __ldg(&b2[0]);
    #pragma unroll
    for (int j = 0; j < 5; ++j) {
        float t = __ldg(&b1[j]);
        #pragma unroll
        for (int k = 0; k < 5; ++k) t += h[k] * __ldg(&W1[k * 5 + j]);
        t = (t > 0.f) ? t : 0.1f * t;
        o += t * __ldg(&W2[j]);
    }
    out[i] = o;

    // reset scratch for the next replay
    g_sum[i] = make_float4(0.f, 0.f, 0.f, 0.f);
    g_cnt[i] = 0.f;
}

extern "C" void kernel_launch(void* const* d_in, const int* in_sizes, int n_in,
                              void* d_out, int out_size) {
    const float* x     = (const float*)d_in[0];
    const int*   batch = (const int*)d_in[1];
    const float* u     = (const float*)d_in[2];
    const float* W1    = (const float*)d_in[3];
    const float* b1    = (const float*)d_in[4];
    const float* W2    = (const float*)d_in[5];
    const float* b2    = (const float*)d_in[6];
    float* out = (float*)d_out;

    int n = in_sizes[1];  // number of nodes

    long long nwarps  = ((long long)n + (32 * ITEMS) - 1) / (32 * ITEMS);
    int       nblocks = (int)((nwarps + (TPB / 32) - 1) / (TPB / 32));
    if (nblocks < 1) nblocks = 1;

    seg_reduce_kernel<<<nblocks, TPB>>>((const float4*)x, batch, n);
    mlp_kernel<<<(BN + TPB - 1) / TPB, TPB>>>(u, W1, b1, W2, b2, out);
}

// round 6
// speedup vs baseline: 2.1664x; 2.1664x over previous
#include <cuda_runtime.h>

#define BN  16384   // number of segments
#define TPB 256
#define IT  8       // int4-chunks per lane per warp tile (warp tile = 32*IT*4 = 1024 elems)

// Segment start offsets. g_start[s] = first node index of segment s; g_start[BN] = n.
// Fully rewritten on every launch (no reset pass needed). No cudaMalloc.
__device__ int g_start[BN + 1];

__device__ __forceinline__ void fill_range(int u, int v, int i) {
    // batch is sorted: for every s in (u, v], segment s starts at node i.
    int s  = (u + 1 > 0)  ? u + 1 : 0;
    int se = (v < BN)     ? v     : BN;
    for (; s <= se; ++s) g_start[s] = i;
}

// ---------------- phase A: boundary detection over batch (20 MB) ----------------
__global__ void __launch_bounds__(TPB) boundaries_kernel(
    const int4* __restrict__ bat4,
    const int*  __restrict__ batch,
    int n)
{
    const int lane = threadIdx.x & 31;
    const int warp = blockIdx.x * (TPB / 32) + (threadIdx.x >> 5);
    const int nchunks = n >> 2;           // full int4 chunks
    const int c0 = warp * (32 * IT);

    if (c0 < nchunks) {
        int carry = (c0 == 0) ? -1 : batch[c0 * 4 - 1];  // element before this warp tile
        #pragma unroll
        for (int it = 0; it < IT; ++it) {
            int  c   = c0 + it * 32 + lane;
            bool act = (c < nchunks);
            int4 b   = make_int4(0, 0, 0, 0);
            if (act) b = bat4[c];

            int pl   = __shfl_up_sync(0xffffffffu, b.w, 1);
            int prev = (lane == 0) ? carry : pl;

            if (act) {
                if ((prev ^ b.x) | (b.x ^ b.y) | (b.y ^ b.z) | (b.z ^ b.w)) {
                    int i = c * 4;
                    fill_range(prev, b.x, i);
                    fill_range(b.x,  b.y, i + 1);
                    fill_range(b.y,  b.z, i + 2);
                    fill_range(b.z,  b.w, i + 3);
                }
            }
            carry = __shfl_sync(0xffffffffu, b.w, 31);
        }
    }

    // One thread handles the scalar tail (< 4 elems) and the end sentinel.
    if (blockIdx.x == 0 && threadIdx.x == 0) {
        int i0   = nchunks * 4;
        int prev = (i0 == 0) ? -1 : batch[i0 - 1];
        for (int i = i0; i < n; ++i) {
            int b = batch[i];
            fill_range(prev, b, i);
            prev = b;
        }
        fill_range(prev, BN, n);   // g_start[s]=n for all s past the last segment, incl. sentinel
    }
}

// -------- phase B: per-segment contiguous sum + fused MLP (reads x, 80 MB) --------
__global__ void __launch_bounds__(TPB) segmean_mlp_kernel(
    const float4* __restrict__ x,
    const float*  __restrict__ u,
    const float*  __restrict__ W1,  // [5,5] row-major
    const float*  __restrict__ b1,  // [5]
    const float*  __restrict__ W2,  // [5,1]
    const float*  __restrict__ b2,  // [1]
    float* __restrict__ out)
{
    const int seg  = blockIdx.x * (TPB / 32) + (threadIdx.x >> 5);
    if (seg >= BN) return;
    const int lane = threadIdx.x & 31;

    const int s = g_start[seg];
    const int e = g_start[seg + 1];

    float4 a0 = make_float4(0.f, 0.f, 0.f, 0.f);
    float4 a1 = make_float4(0.f, 0.f, 0.f, 0.f);

    int i = s + lane;
    // unrolled-by-2 streaming: independent loads, independent accumulators
    for (; i + 32 < e; i += 64) {
        float4 v0 = __ldcs(&x[i]);
        float4 v1 = __ldcs(&x[i + 32]);
        a0.x += v0.x; a0.y += v0.y; a0.z += v0.z; a0.w += v0.w;
        a1.x += v1.x; a1.y += v1.y; a1.z += v1.z; a1.w += v1.w;
    }
    if (i < e) {
        float4 v0 = __ldcs(&x[i]);
        a0.x += v0.x; a0.y += v0.y; a0.z += v0.z; a0.w += v0.w;
    }
    a0.x += a1.x; a0.y += a1.y; a0.z += a1.z; a0.w += a1.w;

    // warp reduction (deterministic tree)
    #pragma unroll
    for (int o = 16; o > 0; o >>= 1) {
        a0.x += __shfl_down_sync(0xffffffffu, a0.x, o);
        a0.y += __shfl_down_sync(0xffffffffu, a0.y, o);
        a0.z += __shfl_down_sync(0xffffffffu, a0.z, o);
        a0.w += __shfl_down_sync(0xffffffffu, a0.w, o);
    }

    if (lane == 0) {
        float cnt = (float)(e - s);
        float inv = (cnt > 0.f) ? (1.f / cnt) : 0.f;

        float h[5];
        h[0] = __ldg(&u[seg]);
        h[1] = a0.x * inv; h[2] = a0.y * inv;
        h[3] = a0.z * inv; h[4] = a0.w * inv;

        float o = __ldg(&b2[0]);
        #pragma unroll
        for (int j = 0; j < 5; ++j) {
            float t = __ldg(&b1[j]);
            #pragma unroll
            for (int k = 0; k < 5; ++k) t += h[k] * __ldg(&W1[k * 5 + j]);
            t = (t > 0.f) ? t : 0.1f * t;
            o += t * __ldg(&W2[j]);
        }
        out[seg] = o;
    }
}

extern "C" void kernel_launch(void* const* d_in, const int* in_sizes, int n_in,
                              void* d_out, int out_size) {
    const float* x     = (const float*)d_in[0];
    const int*   batch = (const int*)d_in[1];
    const float* u     = (const float*)d_in[2];
    const float* W1    = (const float*)d_in[3];
    const float* b1    = (const float*)d_in[4];
    const float* W2    = (const float*)d_in[5];
    const float* b2    = (const float*)d_in[6];
    float* out = (float*)d_out;

    int n = in_sizes[1];  // number of nodes

    // phase A: boundary detection
    {
        int nchunks = n >> 2;
        long long nwarps = ((long long)nchunks + (32 * IT) - 1) / (32 * IT);
        int nblocks = (int)((nwarps + (TPB / 32) - 1) / (TPB / 32));
        if (nblocks < 1) nblocks = 1;
        boundaries_kernel<<<nblocks, TPB>>>((const int4*)batch, batch, n);
    }

    // phase B: one warp per segment, sum + MLP fused
    {
        int nblocks = BN / (TPB / 32);   // 2048
        segmean_mlp_kernel<<<nblocks, TPB>>>((const float4*)x, u, W1, b1, W2, b2, out);
    }
}